// round 16
// baseline (speedup 1.0000x reference)
#include <cuda_runtime.h>
#include <math.h>

#define B_  8
#define C_  512
#define T_  2048
#define G_  32
#define H_  8
#define CH_ 64

// ---------------- scratch (device globals: no allocations allowed) ----------
__device__ float g_h  [(size_t)B_ * C_ * T_];       //  33.5 MB  groupnorm output
__device__ float g_qkv[(size_t)B_ * 3 * C_ * T_];   // 100.7 MB  qkv (q,k pre-scaled)
__device__ float g_a  [(size_t)B_ * C_ * T_];       //  33.5 MB  attention output

// ============================================================================
// 1) GroupNorm(32, C): each (b,g) group is a CONTIGUOUS 16*2048-float chunk.
//    One block per group, two passes (stats then normalize).
// ============================================================================
__global__ void gn_kernel(const float* __restrict__ x,
                          const float* __restrict__ gw,
                          const float* __restrict__ gb,
                          float* __restrict__ h)
{
    const int blk   = blockIdx.x;
    const int batch = blk >> 5;          // / G_
    const int g     = blk & 31;
    const int CPG   = C_ / G_;           // 16
    const int NELE  = CPG * T_;          // 32768
    const size_t base = (size_t)batch * C_ * T_ + (size_t)g * CPG * T_;

    const float4* xv = reinterpret_cast<const float4*>(x + base);
    const int n4 = NELE / 4;             // 8192

    float s = 0.f, ss = 0.f;
    for (int i = threadIdx.x; i < n4; i += blockDim.x) {
        float4 v = xv[i];
        s  += v.x + v.y + v.z + v.w;
        ss += v.x*v.x + v.y*v.y + v.z*v.z + v.w*v.w;
    }
    __shared__ float rs[256], rq[256];
    rs[threadIdx.x] = s;  rq[threadIdx.x] = ss;
    __syncthreads();
    for (int o = 128; o > 0; o >>= 1) {
        if (threadIdx.x < o) {
            rs[threadIdx.x] += rs[threadIdx.x + o];
            rq[threadIdx.x] += rq[threadIdx.x + o];
        }
        __syncthreads();
    }
    __shared__ float mu_s, inv_s;
    if (threadIdx.x == 0) {
        float mu  = rs[0] / (float)NELE;
        float var = rq[0] / (float)NELE - mu * mu;
        mu_s  = mu;
        inv_s = rsqrtf(var + 1e-5f);
    }
    __syncthreads();
    const float mu = mu_s, inv = inv_s;

    float4* hv = reinterpret_cast<float4*>(h + base);
    for (int i = threadIdx.x; i < n4; i += blockDim.x) {
        int   c  = g * CPG + (i >> 9);           // i*4 / T_ (T_/4 = 512)
        float a  = gw[c] * inv;
        float bb = gb[c] - mu * a;               // (x-mu)*inv*w + b  ==  x*a + bb
        float4 v = xv[i];
        v.x = v.x * a + bb;  v.y = v.y * a + bb;
        v.z = v.z * a + bb;  v.w = v.w * a + bb;
        hv[i] = v;
    }
}

// ============================================================================
// 2/4) Batched SGEMM: out[b,m,n] = sum_k W[m,k] * X[b,k,n] + bias[m]
//      rows m < scaledRows get *scale (q/k pre-scale); optional residual R.
//      BM=BN=128, BK=8, 256 threads, 8x8 microtile (FMA-bound ratio 64/16).
// ============================================================================
#define BM 128
#define BN 128
#define BK 8

__global__ __launch_bounds__(256)
void gemm_kernel(const float* __restrict__ W, const float* __restrict__ X,
                 const float* __restrict__ bias, const float* __restrict__ R,
                 float* __restrict__ out,
                 int M, int K, int N, float scale, int scaledRows)
{
    const int b  = blockIdx.z;
    const int m0 = blockIdx.y * BM;
    const int n0 = blockIdx.x * BN;
    const float* Xb = X + (size_t)b * K * N;
    float*       Ob = out + (size_t)b * M * N;
    const float* Rb = R ? (R + (size_t)b * M * N) : nullptr;

    __shared__ float Ws[BK][BM];   // transposed: Ws[k][m]
    __shared__ float Xs[BK][BN];

    const int tid = threadIdx.x;
    const int ty = tid >> 4, tx = tid & 15;
    const int mb = ty * 8,  nb = tx * 8;

    // loader indexing
    const int wRow = tid >> 1;           // 0..127
    const int wCol = (tid & 1) * 4;      // 0 or 4
    const int xRow = tid >> 5;           // 0..7
    const int xCol = (tid & 31) * 4;     // 0..124

    float acc[8][8];
#pragma unroll
    for (int i = 0; i < 8; i++)
#pragma unroll
        for (int j = 0; j < 8; j++) acc[i][j] = 0.f;

    for (int k0 = 0; k0 < K; k0 += BK) {
        float4 wv = *reinterpret_cast<const float4*>(W + (size_t)(m0 + wRow) * K + k0 + wCol);
        Ws[wCol + 0][wRow] = wv.x;
        Ws[wCol + 1][wRow] = wv.y;
        Ws[wCol + 2][wRow] = wv.z;
        Ws[wCol + 3][wRow] = wv.w;
        *reinterpret_cast<float4*>(&Xs[xRow][xCol]) =
            *reinterpret_cast<const float4*>(Xb + (size_t)(k0 + xRow) * N + n0 + xCol);
        __syncthreads();

#pragma unroll
        for (int k = 0; k < BK; k++) {
            float a[8], c[8];
            *reinterpret_cast<float4*>(a)     = *reinterpret_cast<const float4*>(&Ws[k][mb]);
            *reinterpret_cast<float4*>(a + 4) = *reinterpret_cast<const float4*>(&Ws[k][mb + 4]);
            *reinterpret_cast<float4*>(c)     = *reinterpret_cast<const float4*>(&Xs[k][nb]);
            *reinterpret_cast<float4*>(c + 4) = *reinterpret_cast<const float4*>(&Xs[k][nb + 4]);
#pragma unroll
            for (int i = 0; i < 8; i++)
#pragma unroll
                for (int j = 0; j < 8; j++)
                    acc[i][j] = fmaf(a[i], c[j], acc[i][j]);
        }
        __syncthreads();
    }

#pragma unroll
    for (int i = 0; i < 8; i++) {
        const int m = m0 + mb + i;
        float bi = bias[m];
        bool  sc = (m < scaledRows);
#pragma unroll
        for (int j = 0; j < 8; j++) {
            const int n = n0 + nb + j;
            float v = acc[i][j] + bi;
            if (sc) v *= scale;
            size_t idx = (size_t)m * N + n;
            if (Rb) v += Rb[idx];
            Ob[idx] = v;
        }
    }
}

// ============================================================================
// 3) Flash attention.  q,k,v are [bh, ch=64, T] slices of g_qkv (q,k already
//    scaled by ch^-0.25).  Block = (q-tile of 64 cols, bh).  Online softmax
//    over 32 s-tiles of 64.  Smem: Q,K,V,S,P each [64][65] + m/l/alpha.
// ============================================================================
#define AST 65   // smem stride (64 + 1 pad)

__global__ __launch_bounds__(256)
void attn_kernel(const float* __restrict__ qkv, float* __restrict__ aout)
{
    extern __shared__ float sm[];
    float* Qs   = sm;                 // 64*AST
    float* Ks   = Qs + 64 * AST;
    float* Vs   = Ks + 64 * AST;
    float* Ss   = Vs + 64 * AST;      // S[tq][ts]
    float* Ps   = Ss + 64 * AST;      // P[ts][tq]  (transposed exp(S))
    float* mbuf = Ps + 64 * AST;      // 64
    float* lbuf = mbuf + 64;          // 64
    float* abuf = lbuf + 64;          // 64

    const int bh  = blockIdx.y;
    const int b   = bh >> 3;
    const int hh  = bh & 7;
    const int tq0 = blockIdx.x * 64;

    const size_t qoff = (size_t)b * 3 * C_ * T_ + (size_t)hh * CH_ * T_;
    const float* Qp = qkv + qoff;
    const float* Kp = qkv + qoff + (size_t)C_ * T_;
    const float* Vp = qkv + qoff + (size_t)2 * C_ * T_;

    const int tid  = threadIdx.x;
    const int ty   = tid >> 4, tx = tid & 15;
    const int warp = tid >> 5, lane = tid & 31;

    // load Q tile: Qs[c][tq]
    const int lr = tid >> 4;            // 0..15
    const int lc = (tid & 15) * 4;      // 0..60
    for (int r = lr; r < 64; r += 16) {
        float4 v = *reinterpret_cast<const float4*>(Qp + (size_t)r * T_ + tq0 + lc);
        Qs[r * AST + lc + 0] = v.x;  Qs[r * AST + lc + 1] = v.y;
        Qs[r * AST + lc + 2] = v.z;  Qs[r * AST + lc + 3] = v.w;
    }
    if (tid < 64) { mbuf[tid] = -INFINITY; lbuf[tid] = 0.f; }

    float O[16];                        // O[c=ty*4+i][tq=tx*4+j]
#pragma unroll
    for (int i = 0; i < 16; i++) O[i] = 0.f;

    for (int s0 = 0; s0 < T_; s0 += 64) {
        __syncthreads();   // prev GEMM2 done (and Q/init visible on iter 0)
        for (int r = lr; r < 64; r += 16) {
            float4 kv = *reinterpret_cast<const float4*>(Kp + (size_t)r * T_ + s0 + lc);
            Ks[r * AST + lc + 0] = kv.x;  Ks[r * AST + lc + 1] = kv.y;
            Ks[r * AST + lc + 2] = kv.z;  Ks[r * AST + lc + 3] = kv.w;
            float4 vv = *reinterpret_cast<const float4*>(Vp + (size_t)r * T_ + s0 + lc);
            Vs[r * AST + lc + 0] = vv.x;  Vs[r * AST + lc + 1] = vv.y;
            Vs[r * AST + lc + 2] = vv.z;  Vs[r * AST + lc + 3] = vv.w;
        }
        __syncthreads();

        // ---- GEMM1: S[tq][ts] = sum_c Q[c][tq] * K[c][ts] ----
        float sa[4][4];
#pragma unroll
        for (int i = 0; i < 4; i++)
#pragma unroll
            for (int j = 0; j < 4; j++) sa[i][j] = 0.f;
#pragma unroll 8
        for (int c = 0; c < 64; c++) {
            float qv[4], kv[4];
#pragma unroll
            for (int i = 0; i < 4; i++) qv[i] = Qs[c * AST + ty * 4 + i];
#pragma unroll
            for (int j = 0; j < 4; j++) kv[j] = Ks[c * AST + tx * 4 + j];
#pragma unroll
            for (int i = 0; i < 4; i++)
#pragma unroll
                for (int j = 0; j < 4; j++)
                    sa[i][j] = fmaf(qv[i], kv[j], sa[i][j]);
        }
#pragma unroll
        for (int i = 0; i < 4; i++)
#pragma unroll
            for (int j = 0; j < 4; j++)
                Ss[(ty * 4 + i) * AST + tx * 4 + j] = sa[i][j];
        __syncthreads();

        // ---- online softmax: warp w owns rows w*8..w*8+7 ----
        for (int k = 0; k < 8; k++) {
            const int r = warp * 8 + k;
            float v0 = Ss[r * AST + lane];
            float v1 = Ss[r * AST + lane + 32];
            float mx = fmaxf(v0, v1);
#pragma unroll
            for (int off = 16; off > 0; off >>= 1)
                mx = fmaxf(mx, __shfl_xor_sync(0xffffffffu, mx, off));
            const float mo = mbuf[r];
            const float mn = fmaxf(mo, mx);
            float p0 = __expf(v0 - mn);
            float p1 = __expf(v1 - mn);
            Ps[lane * AST + r]        = p0;   // transposed store, conflict-free (odd stride)
            Ps[(lane + 32) * AST + r] = p1;
            float sum = p0 + p1;
#pragma unroll
            for (int off = 16; off > 0; off >>= 1)
                sum += __shfl_xor_sync(0xffffffffu, sum, off);
            if (lane == 0) {
                float al = __expf(mo - mn);
                lbuf[r] = lbuf[r] * al + sum;
                mbuf[r] = mn;
                abuf[r] = al;
            }
        }
        __syncthreads();

        // ---- rescale O, then GEMM2: O[c][tq] += sum_s P[tq][s]*V[c][s] ----
        float al[4];
#pragma unroll
        for (int j = 0; j < 4; j++) al[j] = abuf[tx * 4 + j];
#pragma unroll
        for (int i = 0; i < 4; i++)
#pragma unroll
            for (int j = 0; j < 4; j++) O[i * 4 + j] *= al[j];

#pragma unroll 8
        for (int s = 0; s < 64; s++) {
            float vv[4], pp[4];
#pragma unroll
            for (int i = 0; i < 4; i++) vv[i] = Vs[(ty * 4 + i) * AST + s];
#pragma unroll
            for (int j = 0; j < 4; j++) pp[j] = Ps[s * AST + tx * 4 + j];
#pragma unroll
            for (int i = 0; i < 4; i++)
#pragma unroll
                for (int j = 0; j < 4; j++)
                    O[i * 4 + j] = fmaf(vv[i], pp[j], O[i * 4 + j]);
        }
    }
    __syncthreads();

    // epilogue: a[b, hh*64 + c, tq0 + tq] = O / l[tq]
    float linv[4];
#pragma unroll
    for (int j = 0; j < 4; j++) linv[j] = 1.f / lbuf[tx * 4 + j];
    const size_t obase = (size_t)b * C_ * T_ + (size_t)(hh * CH_) * T_;
#pragma unroll
    for (int i = 0; i < 4; i++) {
        const size_t rowo = obase + (size_t)(ty * 4 + i) * T_ + tq0 + tx * 4;
#pragma unroll
        for (int j = 0; j < 4; j++)
            aout[rowo + j] = O[i * 4 + j] * linv[j];
    }
}

// ============================================================================
// launch
// ============================================================================
extern "C" void kernel_launch(void* const* d_in, const int* in_sizes, int n_in,
                              void* d_out, int out_size)
{
    const float* x      = (const float*)d_in[0];
    const float* gn_w   = (const float*)d_in[1];
    const float* gn_b   = (const float*)d_in[2];
    const float* qkv_w  = (const float*)d_in[3];
    const float* qkv_b  = (const float*)d_in[4];
    const float* proj_w = (const float*)d_in[5];
    const float* proj_b = (const float*)d_in[6];
    float* out = (float*)d_out;

    float *hp, *qkvp, *ap;
    cudaGetSymbolAddress((void**)&hp,   g_h);
    cudaGetSymbolAddress((void**)&qkvp, g_qkv);
    cudaGetSymbolAddress((void**)&ap,   g_a);

    // 1) GroupNorm
    gn_kernel<<<B_ * G_, 256>>>(x, gn_w, gn_b, hp);

    // 2) QKV GEMM (q,k rows scaled by ch^-0.25)
    {
        dim3 grid(T_ / BN, (3 * C_) / BM, B_);
        const float scale = 0.35355339059327373f;   // 64^-0.25
        gemm_kernel<<<grid, 256>>>(qkv_w, hp, qkv_b, nullptr, qkvp,
                                   3 * C_, C_, T_, scale, 2 * C_);
    }

    // 3) flash attention
    {
        const int smem = (5 * 64 * AST + 3 * 64) * (int)sizeof(float);  // 83968 B
        cudaFuncSetAttribute(attn_kernel, cudaFuncAttributeMaxDynamicSharedMemorySize, smem);
        dim3 grid(T_ / 64, B_ * H_);
        attn_kernel<<<grid, 256, smem>>>(qkvp, ap);
    }

    // 4) proj GEMM + bias + residual
    {
        dim3 grid(T_ / BN, C_ / BM, B_);
        gemm_kernel<<<grid, 256>>>(proj_w, ap, proj_b, x, out,
                                   C_, C_, T_, 1.0f, 0);
    }
}

// round 17
// speedup vs baseline: 1.0057x; 1.0057x over previous
#include <cuda_runtime.h>
#include <math.h>

#define B_  8
#define C_  512
#define T_  2048
#define G_  32
#define H_  8
#define CH_ 64

// ---------------- scratch (device globals: no allocations allowed) ----------
__device__ float g_h  [(size_t)B_ * C_ * T_];       //  33.5 MB  groupnorm output
__device__ float g_qkv[(size_t)B_ * 3 * C_ * T_];   // 100.7 MB  qkv (q,k pre-scaled)
__device__ float g_a  [(size_t)B_ * C_ * T_];       //  33.5 MB  attention output

// ============================================================================
// 1) GroupNorm(32, C): each (b,g) group is a CONTIGUOUS 16*2048-float chunk.
//    One block per group, two passes (stats then normalize).
// ============================================================================
__global__ void gn_kernel(const float* __restrict__ x,
                          const float* __restrict__ gw,
                          const float* __restrict__ gb,
                          float* __restrict__ h)
{
    const int blk   = blockIdx.x;
    const int batch = blk >> 5;          // / G_
    const int g     = blk & 31;
    const int CPG   = C_ / G_;           // 16
    const int NELE  = CPG * T_;          // 32768
    const size_t base = (size_t)batch * C_ * T_ + (size_t)g * CPG * T_;

    const float4* xv = reinterpret_cast<const float4*>(x + base);
    const int n4 = NELE / 4;             // 8192

    float s = 0.f, ss = 0.f;
    for (int i = threadIdx.x; i < n4; i += blockDim.x) {
        float4 v = xv[i];
        s  += v.x + v.y + v.z + v.w;
        ss += v.x*v.x + v.y*v.y + v.z*v.z + v.w*v.w;
    }
    __shared__ float rs[256], rq[256];
    rs[threadIdx.x] = s;  rq[threadIdx.x] = ss;
    __syncthreads();
    for (int o = 128; o > 0; o >>= 1) {
        if (threadIdx.x < o) {
            rs[threadIdx.x] += rs[threadIdx.x + o];
            rq[threadIdx.x] += rq[threadIdx.x + o];
        }
        __syncthreads();
    }
    __shared__ float mu_s, inv_s;
    if (threadIdx.x == 0) {
        float mu  = rs[0] / (float)NELE;
        float var = rq[0] / (float)NELE - mu * mu;
        mu_s  = mu;
        inv_s = rsqrtf(var + 1e-5f);
    }
    __syncthreads();
    const float mu = mu_s, inv = inv_s;

    float4* hv = reinterpret_cast<float4*>(h + base);
    for (int i = threadIdx.x; i < n4; i += blockDim.x) {
        int   c  = g * CPG + (i >> 9);           // i*4 / T_ (T_/4 = 512)
        float a  = gw[c] * inv;
        float bb = gb[c] - mu * a;               // (x-mu)*inv*w + b  ==  x*a + bb
        float4 v = xv[i];
        v.x = v.x * a + bb;  v.y = v.y * a + bb;
        v.z = v.z * a + bb;  v.w = v.w * a + bb;
        hv[i] = v;
    }
}

// ============================================================================
// 2/4) Batched SGEMM: out[b,m,n] = sum_k W[m,k] * X[b,k,n] + bias[m]
//      rows m < scaledRows get *scale (q/k pre-scale); optional residual R.
//      BM=BN=128, BK=8, 256 threads, 8x8 microtile (FMA-bound ratio 64/16).
// ============================================================================
#define BM 128
#define BN 128
#define BK 8

__global__ __launch_bounds__(256)
void gemm_kernel(const float* __restrict__ W, const float* __restrict__ X,
                 const float* __restrict__ bias, const float* __restrict__ R,
                 float* __restrict__ out,
                 int M, int K, int N, float scale, int scaledRows)
{
    const int b  = blockIdx.z;
    const int m0 = blockIdx.y * BM;
    const int n0 = blockIdx.x * BN;
    const float* Xb = X + (size_t)b * K * N;
    float*       Ob = out + (size_t)b * M * N;
    const float* Rb = R ? (R + (size_t)b * M * N) : nullptr;

    __shared__ float Ws[BK][BM];   // transposed: Ws[k][m]
    __shared__ float Xs[BK][BN];

    const int tid = threadIdx.x;
    const int ty = tid >> 4, tx = tid & 15;
    const int mb = ty * 8,  nb = tx * 8;

    // loader indexing
    const int wRow = tid >> 1;           // 0..127
    const int wCol = (tid & 1) * 4;      // 0 or 4
    const int xRow = tid >> 5;           // 0..7
    const int xCol = (tid & 31) * 4;     // 0..124

    float acc[8][8];
#pragma unroll
    for (int i = 0; i < 8; i++)
#pragma unroll
        for (int j = 0; j < 8; j++) acc[i][j] = 0.f;

    for (int k0 = 0; k0 < K; k0 += BK) {
        float4 wv = *reinterpret_cast<const float4*>(W + (size_t)(m0 + wRow) * K + k0 + wCol);
        Ws[wCol + 0][wRow] = wv.x;
        Ws[wCol + 1][wRow] = wv.y;
        Ws[wCol + 2][wRow] = wv.z;
        Ws[wCol + 3][wRow] = wv.w;
        *reinterpret_cast<float4*>(&Xs[xRow][xCol]) =
            *reinterpret_cast<const float4*>(Xb + (size_t)(k0 + xRow) * N + n0 + xCol);
        __syncthreads();

#pragma unroll
        for (int k = 0; k < BK; k++) {
            float a[8], c[8];
            *reinterpret_cast<float4*>(a)     = *reinterpret_cast<const float4*>(&Ws[k][mb]);
            *reinterpret_cast<float4*>(a + 4) = *reinterpret_cast<const float4*>(&Ws[k][mb + 4]);
            *reinterpret_cast<float4*>(c)     = *reinterpret_cast<const float4*>(&Xs[k][nb]);
            *reinterpret_cast<float4*>(c + 4) = *reinterpret_cast<const float4*>(&Xs[k][nb + 4]);
#pragma unroll
            for (int i = 0; i < 8; i++)
#pragma unroll
                for (int j = 0; j < 8; j++)
                    acc[i][j] = fmaf(a[i], c[j], acc[i][j]);
        }
        __syncthreads();
    }

#pragma unroll
    for (int i = 0; i < 8; i++) {
        const int m = m0 + mb + i;
        float bi = bias[m];
        bool  sc = (m < scaledRows);
#pragma unroll
        for (int j = 0; j < 8; j++) {
            const int n = n0 + nb + j;
            float v = acc[i][j] + bi;
            if (sc) v *= scale;
            size_t idx = (size_t)m * N + n;
            if (Rb) v += Rb[idx];
            Ob[idx] = v;
        }
    }
}

// ============================================================================
// 3) Flash attention.  q,k,v are [bh, ch=64, T] slices of g_qkv (q,k already
//    scaled by ch^-0.25).  Block = (q-tile of 64 cols, bh).  Online softmax
//    over 32 s-tiles of 64.  Smem: Q,K,V,S,P each [64][65] + m/l/alpha.
// ============================================================================
#define AST 65   // smem stride (64 + 1 pad)

__global__ __launch_bounds__(256)
void attn_kernel(const float* __restrict__ qkv, float* __restrict__ aout)
{
    extern __shared__ float sm[];
    float* Qs   = sm;                 // 64*AST
    float* Ks   = Qs + 64 * AST;
    float* Vs   = Ks + 64 * AST;
    float* Ss   = Vs + 64 * AST;      // S[tq][ts]
    float* Ps   = Ss + 64 * AST;      // P[ts][tq]  (transposed exp(S))
    float* mbuf = Ps + 64 * AST;      // 64
    float* lbuf = mbuf + 64;          // 64
    float* abuf = lbuf + 64;          // 64

    const int bh  = blockIdx.y;
    const int b   = bh >> 3;
    const int hh  = bh & 7;
    const int tq0 = blockIdx.x * 64;

    const size_t qoff = (size_t)b * 3 * C_ * T_ + (size_t)hh * CH_ * T_;
    const float* Qp = qkv + qoff;
    const float* Kp = qkv + qoff + (size_t)C_ * T_;
    const float* Vp = qkv + qoff + (size_t)2 * C_ * T_;

    const int tid  = threadIdx.x;
    const int ty   = tid >> 4, tx = tid & 15;
    const int warp = tid >> 5, lane = tid & 31;

    // load Q tile: Qs[c][tq]
    const int lr = tid >> 4;            // 0..15
    const int lc = (tid & 15) * 4;      // 0..60
    for (int r = lr; r < 64; r += 16) {
        float4 v = *reinterpret_cast<const float4*>(Qp + (size_t)r * T_ + tq0 + lc);
        Qs[r * AST + lc + 0] = v.x;  Qs[r * AST + lc + 1] = v.y;
        Qs[r * AST + lc + 2] = v.z;  Qs[r * AST + lc + 3] = v.w;
    }
    if (tid < 64) { mbuf[tid] = -INFINITY; lbuf[tid] = 0.f; }

    float O[16];                        // O[c=ty*4+i][tq=tx*4+j]
#pragma unroll
    for (int i = 0; i < 16; i++) O[i] = 0.f;

    for (int s0 = 0; s0 < T_; s0 += 64) {
        __syncthreads();   // prev GEMM2 done (and Q/init visible on iter 0)
        for (int r = lr; r < 64; r += 16) {
            float4 kv = *reinterpret_cast<const float4*>(Kp + (size_t)r * T_ + s0 + lc);
            Ks[r * AST + lc + 0] = kv.x;  Ks[r * AST + lc + 1] = kv.y;
            Ks[r * AST + lc + 2] = kv.z;  Ks[r * AST + lc + 3] = kv.w;
            float4 vv = *reinterpret_cast<const float4*>(Vp + (size_t)r * T_ + s0 + lc);
            Vs[r * AST + lc + 0] = vv.x;  Vs[r * AST + lc + 1] = vv.y;
            Vs[r * AST + lc + 2] = vv.z;  Vs[r * AST + lc + 3] = vv.w;
        }
        __syncthreads();

        // ---- GEMM1: S[tq][ts] = sum_c Q[c][tq] * K[c][ts] ----
        float sa[4][4];
#pragma unroll
        for (int i = 0; i < 4; i++)
#pragma unroll
            for (int j = 0; j < 4; j++) sa[i][j] = 0.f;
#pragma unroll 8
        for (int c = 0; c < 64; c++) {
            float qv[4], kv[4];
#pragma unroll
            for (int i = 0; i < 4; i++) qv[i] = Qs[c * AST + ty * 4 + i];
#pragma unroll
            for (int j = 0; j < 4; j++) kv[j] = Ks[c * AST + tx * 4 + j];
#pragma unroll
            for (int i = 0; i < 4; i++)
#pragma unroll
                for (int j = 0; j < 4; j++)
                    sa[i][j] = fmaf(qv[i], kv[j], sa[i][j]);
        }
#pragma unroll
        for (int i = 0; i < 4; i++)
#pragma unroll
            for (int j = 0; j < 4; j++)
                Ss[(ty * 4 + i) * AST + tx * 4 + j] = sa[i][j];
        __syncthreads();

        // ---- online softmax: warp w owns rows w*8..w*8+7 ----
        for (int k = 0; k < 8; k++) {
            const int r = warp * 8 + k;
            float v0 = Ss[r * AST + lane];
            float v1 = Ss[r * AST + lane + 32];
            float mx = fmaxf(v0, v1);
#pragma unroll
            for (int off = 16; off > 0; off >>= 1)
                mx = fmaxf(mx, __shfl_xor_sync(0xffffffffu, mx, off));
            const float mo = mbuf[r];
            const float mn = fmaxf(mo, mx);
            float p0 = __expf(v0 - mn);
            float p1 = __expf(v1 - mn);
            Ps[lane * AST + r]        = p0;   // transposed store, conflict-free (odd stride)
            Ps[(lane + 32) * AST + r] = p1;
            float sum = p0 + p1;
#pragma unroll
            for (int off = 16; off > 0; off >>= 1)
                sum += __shfl_xor_sync(0xffffffffu, sum, off);
            if (lane == 0) {
                float al = __expf(mo - mn);
                lbuf[r] = lbuf[r] * al + sum;
                mbuf[r] = mn;
                abuf[r] = al;
            }
        }
        __syncthreads();

        // ---- rescale O, then GEMM2: O[c][tq] += sum_s P[tq][s]*V[c][s] ----
        float al[4];
#pragma unroll
        for (int j = 0; j < 4; j++) al[j] = abuf[tx * 4 + j];
#pragma unroll
        for (int i = 0; i < 4; i++)
#pragma unroll
            for (int j = 0; j < 4; j++) O[i * 4 + j] *= al[j];

#pragma unroll 8
        for (int s = 0; s < 64; s++) {
            float vv[4], pp[4];
#pragma unroll
            for (int i = 0; i < 4; i++) vv[i] = Vs[(ty * 4 + i) * AST + s];
#pragma unroll
            for (int j = 0; j < 4; j++) pp[j] = Ps[s * AST + tx * 4 + j];
#pragma unroll
            for (int i = 0; i < 4; i++)
#pragma unroll
                for (int j = 0; j < 4; j++)
                    O[i * 4 + j] = fmaf(vv[i], pp[j], O[i * 4 + j]);
        }
    }
    __syncthreads();

    // epilogue: a[b, hh*64 + c, tq0 + tq] = O / l[tq]
    float linv[4];
#pragma unroll
    for (int j = 0; j < 4; j++) linv[j] = 1.f / lbuf[tx * 4 + j];
    const size_t obase = (size_t)b * C_ * T_ + (size_t)(hh * CH_) * T_;
#pragma unroll
    for (int i = 0; i < 4; i++) {
        const size_t rowo = obase + (size_t)(ty * 4 + i) * T_ + tq0 + tx * 4;
#pragma unroll
        for (int j = 0; j < 4; j++)
            aout[rowo + j] = O[i * 4 + j] * linv[j];
    }
}

// ============================================================================
// launch
// ============================================================================
extern "C" void kernel_launch(void* const* d_in, const int* in_sizes, int n_in,
                              void* d_out, int out_size)
{
    const float* x      = (const float*)d_in[0];
    const float* gn_w   = (const float*)d_in[1];
    const float* gn_b   = (const float*)d_in[2];
    const float* qkv_w  = (const float*)d_in[3];
    const float* qkv_b  = (const float*)d_in[4];
    const float* proj_w = (const float*)d_in[5];
    const float* proj_b = (const float*)d_in[6];
    float* out = (float*)d_out;

    float *hp, *qkvp, *ap;
    cudaGetSymbolAddress((void**)&hp,   g_h);
    cudaGetSymbolAddress((void**)&qkvp, g_qkv);
    cudaGetSymbolAddress((void**)&ap,   g_a);

    // 1) GroupNorm
    gn_kernel<<<B_ * G_, 256>>>(x, gn_w, gn_b, hp);

    // 2) QKV GEMM (q,k rows scaled by ch^-0.25)
    {
        dim3 grid(T_ / BN, (3 * C_) / BM, B_);
        const float scale = 0.35355339059327373f;   // 64^-0.25
        gemm_kernel<<<grid, 256>>>(qkv_w, hp, qkv_b, nullptr, qkvp,
                                   3 * C_, C_, T_, scale, 2 * C_);
    }

    // 3) flash attention
    {
        const int smem = (5 * 64 * AST + 3 * 64) * (int)sizeof(float);  // 83968 B
        cudaFuncSetAttribute(attn_kernel, cudaFuncAttributeMaxDynamicSharedMemorySize, smem);
        dim3 grid(T_ / 64, B_ * H_);
        attn_kernel<<<grid, 256, smem>>>(qkvp, ap);
    }

    // 4) proj GEMM + bias + residual
    {
        dim3 grid(T_ / BN, C_ / BM, B_);
        gemm_kernel<<<grid, 256>>>(proj_w, ap, proj_b, x, out,
                                   C_, C_, T_, 1.0f, 0);
    }
}